// round 7
// baseline (speedup 1.0000x reference)
#include <cuda_runtime.h>

#define NN 100000
#define NE 1600000
#define NF 128
#define KCH 4
#define PD 32
#define HID 128
#define TN 64

// ---- device-global scratch (no allocs allowed) ----
__device__ float g_C[(size_t)NN * HID];   // c[n][k*32+p]
__device__ float g_acol[NN * 4];
__device__ float g_arow[NN * 4];
__device__ float g_Wbig[NF * HID];        // Wbig[f][k*32+p]
__device__ float g_bcomb[HID];
// CSR-by-destination scratch
__device__ int g_cnt[NN];
__device__ int g_start[NN + 1];
__device__ int g_cursor[NN];
__device__ int g_ecc[NE];                 // ecol of each edge, bucketed by erow

// ---------------------------------------------------------------------------
// Kernel 0: Wbig = Wlin @ Wconv per channel (folded), bcomb = blin @ Wconv
// ---------------------------------------------------------------------------
__global__ void k_combine(const float* __restrict__ Wlin,
                          const float* __restrict__ blin,
                          const float* __restrict__ Wconv) {
    int f  = blockIdx.x;
    int kp = threadIdx.x;          // 0..127
    int k = kp >> 5, p = kp & 31;
    float s = 0.f;
    const float* wc = Wconv + (size_t)k * PD * PD + p;
    if (f < NF) {
        const float* wl = Wlin + ((size_t)k * NF + f) * PD;
#pragma unroll
        for (int q = 0; q < PD; q++) s = fmaf(wl[q], wc[q * PD], s);
        g_Wbig[f * HID + kp] = s;
    } else {
        const float* bl = blin + k * PD;
#pragma unroll
        for (int q = 0; q < PD; q++) s = fmaf(bl[q], wc[q * PD], s);
        g_bcomb[kp] = s;
    }
}

// ---------------------------------------------------------------------------
// Kernel 1: fused  C = x @ Wbig + bcomb  AND  acol/arow = x @ aW1 halves.
// ---------------------------------------------------------------------------
__global__ __launch_bounds__(256) void k_gemm(const float* __restrict__ x,
                                              const float* __restrict__ aW1) {
    __shared__ float xs[NF][TN + 1];   // k-major x tile, +1 pad
    const int n0 = blockIdx.x * TN;
    const int tid = threadIdx.x;

    for (int i = tid; i < TN * 32; i += 256) {
        int n = i >> 5;
        int f4 = i & 31;
        float4 v = make_float4(0.f, 0.f, 0.f, 0.f);
        int gn = n0 + n;
        if (gn < NN) v = __ldg((const float4*)(x + (size_t)gn * NF + f4 * 4));
        xs[f4 * 4 + 0][n] = v.x;
        xs[f4 * 4 + 1][n] = v.y;
        xs[f4 * 4 + 2][n] = v.z;
        xs[f4 * 4 + 3][n] = v.w;
    }
    __syncthreads();

    const int tx = tid & 31;
    const int ty = tid >> 5;
    const int c0 = tx * 4;
    float acc[8][4];
#pragma unroll
    for (int j = 0; j < 8; j++) { acc[j][0] = acc[j][1] = acc[j][2] = acc[j][3] = 0.f; }

    const float4* W4 = (const float4*)g_Wbig;
#pragma unroll 4
    for (int k = 0; k < NF; k++) {
        float4 w = __ldg(&W4[k * 32 + tx]);
#pragma unroll
        for (int j = 0; j < 8; j++) {
            float xv = xs[k][ty * 8 + j];
            acc[j][0] = fmaf(xv, w.x, acc[j][0]);
            acc[j][1] = fmaf(xv, w.y, acc[j][1]);
            acc[j][2] = fmaf(xv, w.z, acc[j][2]);
            acc[j][3] = fmaf(xv, w.w, acc[j][3]);
        }
    }

    float4 bc = __ldg(&((const float4*)g_bcomb)[tx]);
#pragma unroll
    for (int j = 0; j < 8; j++) {
        int n = n0 + ty * 8 + j;
        if (n < NN) {
            float4 o = make_float4(acc[j][0] + bc.x, acc[j][1] + bc.y,
                                   acc[j][2] + bc.z, acc[j][3] + bc.w);
            *(float4*)(g_C + (size_t)n * HID + c0) = o;
        }
    }

    // ---- assigner projections from the same x tile ----
#pragma unroll
    for (int node_in_ty = 0; node_in_ty < 8; node_in_ty++) {
        int n = ty * 8 + node_in_ty;
        int gn = n0 + n;
        float pc[4] = {0.f, 0.f, 0.f, 0.f};
        float pr[4] = {0.f, 0.f, 0.f, 0.f};
        int f0 = tx * 4;
#pragma unroll
        for (int j = 0; j < 4; j++) {
            float xj = xs[f0 + j][n];
            float4 wc = __ldg((const float4*)(aW1 + (f0 + j) * 4));
            float4 wr = __ldg((const float4*)(aW1 + (128 + f0 + j) * 4));
            pc[0] = fmaf(xj, wc.x, pc[0]); pc[1] = fmaf(xj, wc.y, pc[1]);
            pc[2] = fmaf(xj, wc.z, pc[2]); pc[3] = fmaf(xj, wc.w, pc[3]);
            pr[0] = fmaf(xj, wr.x, pr[0]); pr[1] = fmaf(xj, wr.y, pr[1]);
            pr[2] = fmaf(xj, wr.z, pr[2]); pr[3] = fmaf(xj, wr.w, pr[3]);
        }
#pragma unroll
        for (int o = 16; o > 0; o >>= 1) {
#pragma unroll
            for (int q = 0; q < 4; q++) {
                pc[q] += __shfl_xor_sync(0xffffffffu, pc[q], o);
                pr[q] += __shfl_xor_sync(0xffffffffu, pr[q], o);
            }
        }
        if (tx == 0 && gn < NN) {
            *(float4*)(g_acol + gn * 4) = make_float4(pc[0], pc[1], pc[2], pc[3]);
            *(float4*)(g_arow + gn * 4) = make_float4(pr[0], pr[1], pr[2], pr[3]);
        }
    }
}

// ---------------------------------------------------------------------------
// CSR build: zero -> histogram -> exclusive scan -> scatter (store ecol)
// ---------------------------------------------------------------------------
__global__ void k_zero() {
    int i = blockIdx.x * blockDim.x + threadIdx.x;
    if (i < NN) g_cnt[i] = 0;
}

__global__ void k_hist(const int* __restrict__ erow) {
    int i = blockIdx.x * blockDim.x + threadIdx.x;
    if (i < NE) atomicAdd(&g_cnt[__ldg(erow + i)], 1);
}

// single block, 1024 threads: chunked serial + Hillis-Steele block scan
__global__ __launch_bounds__(1024) void k_scan() {
    __shared__ int ssum[1024];
    const int tid = threadIdx.x;
    const int CHUNK = (NN + 1023) / 1024;
    const int base = tid * CHUNK;

    int s = 0;
    for (int i = 0; i < CHUNK; i++) {
        int idx = base + i;
        if (idx < NN) s += g_cnt[idx];
    }
    ssum[tid] = s;
    __syncthreads();

    // inclusive scan over 1024 chunk sums
    for (int off = 1; off < 1024; off <<= 1) {
        int add = (tid >= off) ? ssum[tid - off] : 0;
        __syncthreads();
        ssum[tid] += add;
        __syncthreads();
    }
    int run = ssum[tid] - s;   // exclusive prefix for this chunk

    for (int i = 0; i < CHUNK; i++) {
        int idx = base + i;
        if (idx < NN) {
            int c = g_cnt[idx];
            g_start[idx]  = run;
            g_cursor[idx] = run;
            run += c;
        }
    }
    if (tid == 1023) g_start[NN] = ssum[1023];
}

__global__ void k_scatter(const int* __restrict__ erow,
                          const int* __restrict__ ecol) {
    int i = blockIdx.x * blockDim.x + threadIdx.x;
    if (i < NE) {
        int p = atomicAdd(&g_cursor[__ldg(erow + i)], 1);
        g_ecc[p] = __ldg(ecol + i);
    }
}

// ---------------------------------------------------------------------------
// Kernel 2: warp-per-node gather-reduce (NO atomics) fused with bias,
// per-channel L2 norm and classifier. 2-stage software pipeline: the next
// edge's {index, acol, g_C-row} are issued before the current edge's compute,
// hiding the dependent 2-hop L2 chain (~480 cyc) behind ALU work.
// ---------------------------------------------------------------------------
__global__ __launch_bounds__(256) void k_node(const float* __restrict__ aW2,
                                              const float* __restrict__ ab1,
                                              const float* __restrict__ ab2,
                                              const float* __restrict__ bch,
                                              const float* __restrict__ Wcls,
                                              const float* __restrict__ bcls,
                                              float* __restrict__ out) {
    const int lane = threadIdx.x & 31;
    const int k = lane >> 3;                      // channel of this lane's float4
    const int n = (blockIdx.x * blockDim.x + threadIdx.x) >> 5;
    if (n >= NN) return;

    // tiny params in registers
    float w2[16];
#pragma unroll
    for (int i = 0; i < 16; i++) w2[i] = __ldg(aW2 + i);
    float b1x = __ldg(ab1 + 0), b1y = __ldg(ab1 + 1), b1z = __ldg(ab1 + 2), b1w = __ldg(ab1 + 3);
    float b2x = __ldg(ab2 + 0), b2y = __ldg(ab2 + 1), b2z = __ldg(ab2 + 2), b2w = __ldg(ab2 + 3);

    const int s_beg = __ldg(&g_start[n]);
    const int s_end = __ldg(&g_start[n + 1]);
    float4 ar = *(const float4*)(g_arow + n * 4);   // one load per node

    float a0 = 0.f, a1 = 0.f, a2 = 0.f, a3 = 0.f;

    if (s_beg < s_end) {
        // pipeline prologue: first edge's full working set
        int cc = __ldg(g_ecc + s_beg);
        float4 ac = __ldg((const float4*)(g_acol + cc * 4));
        float4 cv = __ldg((const float4*)(g_C + (size_t)cc * HID + lane * 4));

        for (int i = s_beg; i < s_end; i++) {
            const float4 ac_c = ac, cv_c = cv;

            // prefetch next edge before compute
            if (i + 1 < s_end) {
                cc = __ldg(g_ecc + i + 1);
                ac = __ldg((const float4*)(g_acol + cc * 4));
                cv = __ldg((const float4*)(g_C + (size_t)cc * HID + lane * 4));
            }

            float h0 = ac_c.x + ar.x + b1x;
            float h1 = ac_c.y + ar.y + b1y;
            float h2 = ac_c.z + ar.z + b1z;
            float h3 = ac_c.w + ar.w + b1w;

            float t0 = fmaf(h0, w2[0], fmaf(h1, w2[4], fmaf(h2, w2[8],  fmaf(h3, w2[12], b2x))));
            float t1 = fmaf(h0, w2[1], fmaf(h1, w2[5], fmaf(h2, w2[9],  fmaf(h3, w2[13], b2y))));
            float t2 = fmaf(h0, w2[2], fmaf(h1, w2[6], fmaf(h2, w2[10], fmaf(h3, w2[14], b2z))));
            float t3 = fmaf(h0, w2[3], fmaf(h1, w2[7], fmaf(h2, w2[11], fmaf(h3, w2[15], b2w))));

            float m = fmaxf(fmaxf(t0, t1), fmaxf(t2, t3));
            float e0 = __expf(t0 - m), e1 = __expf(t1 - m);
            float e2 = __expf(t2 - m), e3 = __expf(t3 - m);
            float inv = 1.f / (e0 + e1 + e2 + e3);
            float wk = ((k == 0) ? e0 : (k == 1) ? e1 : (k == 2) ? e2 : e3) * inv;

            a0 = fmaf(wk, cv_c.x, a0);
            a1 = fmaf(wk, cv_c.y, a1);
            a2 = fmaf(wk, cv_c.z, a2);
            a3 = fmaf(wk, cv_c.w, a3);
        }
    }

    // bias + per-channel L2 normalize
    float4 b = __ldg((const float4*)(bch + lane * 4));
    a0 += b.x; a1 += b.y; a2 += b.z; a3 += b.w;

    float ss = a0 * a0 + a1 * a1 + a2 * a2 + a3 * a3;
    ss += __shfl_xor_sync(0xffffffffu, ss, 1);
    ss += __shfl_xor_sync(0xffffffffu, ss, 2);
    ss += __shfl_xor_sync(0xffffffffu, ss, 4);   // 8-lane group = one channel
    float invn = 1.f / fmaxf(sqrtf(ss), 1e-12f);
    a0 *= invn; a1 *= invn; a2 *= invn; a3 *= invn;

    *(float4*)(out + (size_t)n * HID + lane * 4) = make_float4(a0, a1, a2, a3);

    // classifier
    float4 wc = __ldg((const float4*)(Wcls + lane * 4));
    float p = a0 * wc.x + a1 * wc.y + a2 * wc.z + a3 * wc.w;
#pragma unroll
    for (int o = 16; o > 0; o >>= 1) p += __shfl_xor_sync(0xffffffffu, p, o);
    if (lane == 0) out[(size_t)NN * HID + n] = p + __ldg(bcls);
}

// ---------------------------------------------------------------------------
extern "C" void kernel_launch(void* const* d_in, const int* in_sizes, int n_in,
                              void* d_out, int out_size) {
    const float* x     = (const float*)d_in[0];
    const int*   erow  = (const int*)  d_in[1];
    const int*   ecol  = (const int*)  d_in[2];
    const float* aW1   = (const float*)d_in[3];
    const float* ab1   = (const float*)d_in[4];
    const float* aW2   = (const float*)d_in[5];
    const float* ab2   = (const float*)d_in[6];
    const float* Wlin  = (const float*)d_in[7];
    const float* blin  = (const float*)d_in[8];
    const float* Wconv = (const float*)d_in[9];
    const float* bch   = (const float*)d_in[10];
    const float* Wcls  = (const float*)d_in[11];
    const float* bcls  = (const float*)d_in[12];
    float* out = (float*)d_out;

    k_combine<<<NF + 1, HID>>>(Wlin, blin, Wconv);
    k_zero<<<(NN + 255) / 256, 256>>>();
    k_gemm<<<(NN + TN - 1) / TN, 256>>>(x, aW1);
    k_hist<<<(NE + 255) / 256, 256>>>(erow);
    k_scan<<<1, 1024>>>();
    k_scatter<<<(NE + 255) / 256, 256>>>(erow, ecol);
    k_node<<<(NN * 32 + 255) / 256, 256>>>(aW2, ab1, ab2, bch, Wcls, bcls, out);
}

// round 10
// speedup vs baseline: 1.3114x; 1.3114x over previous
#include <cuda_runtime.h>

#define NN 100000
#define NE 1600000
#define NF 128
#define KCH 4
#define PD 32
#define HID 128
#define TN 64
#define XS_STRIDE 66   // 64 nodes + 2 pad floats: 264B rows, 8B-aligned for float2

// ---- device-global scratch (no allocs allowed) ----
__device__ float g_C[(size_t)NN * HID];   // c[n][k*32+p]
__device__ float g_acol[NN * 4];
__device__ float g_arow[NN * 4];
__device__ float g_Wbig[NF * HID];        // Wbig[f][k*32+p]
__device__ float g_bcomb[HID];
// CSR-by-destination scratch
__device__ int   g_cnt[NN];
__device__ int   g_start[NN + 1];
__device__ int   g_cursor[NN];
__device__ int   g_ecc[NE];               // ecol per CSR slot
__device__ float g_w[(size_t)NE * 4];     // per-edge channel weights per CSR slot

// packed f32x2 helpers (sm_103a dual-FP32 path; PTX-only)
#define PACK_F2(out, lo, hi) \
    asm("mov.b64 %0, {%1, %2};" : "=l"(out) : "r"(__float_as_uint(lo)), "r"(__float_as_uint(hi)))
#define UNPACK_F2(lo, hi, in) \
    do { unsigned int _ulo, _uhi; \
         asm("mov.b64 {%0, %1}, %2;" : "=r"(_ulo), "=r"(_uhi) : "l"(in)); \
         lo = __uint_as_float(_ulo); hi = __uint_as_float(_uhi); } while (0)
#define FMA_F2(d, a, b, c) \
    asm("fma.rn.f32x2 %0, %1, %2, %3;" : "=l"(d) : "l"(a), "l"(b), "l"(c))

// ---------------------------------------------------------------------------
// Kernel 0: Wbig = Wlin @ Wconv per channel (folded), bcomb = blin @ Wconv
// ---------------------------------------------------------------------------
__global__ void k_combine(const float* __restrict__ Wlin,
                          const float* __restrict__ blin,
                          const float* __restrict__ Wconv) {
    int f  = blockIdx.x;
    int kp = threadIdx.x;          // 0..127
    int k = kp >> 5, p = kp & 31;
    float s = 0.f;
    const float* wc = Wconv + (size_t)k * PD * PD + p;
    if (f < NF) {
        const float* wl = Wlin + ((size_t)k * NF + f) * PD;
#pragma unroll
        for (int q = 0; q < PD; q++) s = fmaf(wl[q], wc[q * PD], s);
        g_Wbig[f * HID + kp] = s;
    } else {
        const float* bl = blin + k * PD;
#pragma unroll
        for (int q = 0; q < PD; q++) s = fmaf(bl[q], wc[q * PD], s);
        g_bcomb[kp] = s;
    }
}

// ---------------------------------------------------------------------------
// Kernel 1: fused  C = x @ Wbig + bcomb  AND  acol/arow = x @ aW1 halves.
// Mainloop uses packed fma.rn.f32x2: node-pairs share a weight component, so
// per k-iter the body is 4 LDS.64 + 4 packs + 16 FFMA2 (vs 8 LDS + 32 FFMA).
// ---------------------------------------------------------------------------
__global__ __launch_bounds__(256) void k_gemm(const float* __restrict__ x,
                                              const float* __restrict__ aW1) {
    __shared__ float xs[NF * XS_STRIDE];   // k-major x tile
    const int n0 = blockIdx.x * TN;
    const int tid = threadIdx.x;

    // cooperative load: 64 nodes x 32 float4 each
    for (int i = tid; i < TN * 32; i += 256) {
        int n = i >> 5;
        int f4 = i & 31;
        float4 v = make_float4(0.f, 0.f, 0.f, 0.f);
        int gn = n0 + n;
        if (gn < NN) v = __ldg((const float4*)(x + (size_t)gn * NF + f4 * 4));
        xs[(f4 * 4 + 0) * XS_STRIDE + n] = v.x;
        xs[(f4 * 4 + 1) * XS_STRIDE + n] = v.y;
        xs[(f4 * 4 + 2) * XS_STRIDE + n] = v.z;
        xs[(f4 * 4 + 3) * XS_STRIDE + n] = v.w;
    }
    __syncthreads();

    const int tx = tid & 31;       // column group
    const int ty = tid >> 5;       // node group (0..7)
    const int c0 = tx * 4;

    // acc2[jp][c]: packed pair of accumulators for nodes (2jp, 2jp+1), col c
    unsigned long long acc2[4][4];
#pragma unroll
    for (int jp = 0; jp < 4; jp++)
#pragma unroll
        for (int c = 0; c < 4; c++) acc2[jp][c] = 0ull;

    const float4* W4 = (const float4*)g_Wbig;
#pragma unroll 4
    for (int k = 0; k < NF; k++) {
        float4 w = __ldg(&W4[k * 32 + tx]);
        unsigned long long wx, wy, wz, ww;
        PACK_F2(wx, w.x, w.x);
        PACK_F2(wy, w.y, w.y);
        PACK_F2(wz, w.z, w.z);
        PACK_F2(ww, w.w, w.w);
        const float2* xrow = (const float2*)(xs + k * XS_STRIDE + ty * 8);
#pragma unroll
        for (int jp = 0; jp < 4; jp++) {
            float2 xp = xrow[jp];
            unsigned long long xv;
            PACK_F2(xv, xp.x, xp.y);
            FMA_F2(acc2[jp][0], xv, wx, acc2[jp][0]);
            FMA_F2(acc2[jp][1], xv, wy, acc2[jp][1]);
            FMA_F2(acc2[jp][2], xv, wz, acc2[jp][2]);
            FMA_F2(acc2[jp][3], xv, ww, acc2[jp][3]);
        }
    }

    float4 bc = __ldg(&((const float4*)g_bcomb)[tx]);
#pragma unroll
    for (int jp = 0; jp < 4; jp++) {
        float lo0, hi0, lo1, hi1, lo2, hi2, lo3, hi3;
        UNPACK_F2(lo0, hi0, acc2[jp][0]);
        UNPACK_F2(lo1, hi1, acc2[jp][1]);
        UNPACK_F2(lo2, hi2, acc2[jp][2]);
        UNPACK_F2(lo3, hi3, acc2[jp][3]);
        int nA = n0 + ty * 8 + 2 * jp;
        int nB = nA + 1;
        if (nA < NN) {
            *(float4*)(g_C + (size_t)nA * HID + c0) =
                make_float4(lo0 + bc.x, lo1 + bc.y, lo2 + bc.z, lo3 + bc.w);
        }
        if (nB < NN) {
            *(float4*)(g_C + (size_t)nB * HID + c0) =
                make_float4(hi0 + bc.x, hi1 + bc.y, hi2 + bc.z, hi3 + bc.w);
        }
    }

    // ---- assigner projections from the same x tile ----
#pragma unroll
    for (int node_in_ty = 0; node_in_ty < 8; node_in_ty++) {
        int n = ty * 8 + node_in_ty;
        int gn = n0 + n;
        float pc[4] = {0.f, 0.f, 0.f, 0.f};
        float pr[4] = {0.f, 0.f, 0.f, 0.f};
        int f0 = tx * 4;
#pragma unroll
        for (int j = 0; j < 4; j++) {
            float xj = xs[(f0 + j) * XS_STRIDE + n];
            float4 wc = __ldg((const float4*)(aW1 + (f0 + j) * 4));
            float4 wr = __ldg((const float4*)(aW1 + (128 + f0 + j) * 4));
            pc[0] = fmaf(xj, wc.x, pc[0]); pc[1] = fmaf(xj, wc.y, pc[1]);
            pc[2] = fmaf(xj, wc.z, pc[2]); pc[3] = fmaf(xj, wc.w, pc[3]);
            pr[0] = fmaf(xj, wr.x, pr[0]); pr[1] = fmaf(xj, wr.y, pr[1]);
            pr[2] = fmaf(xj, wr.z, pr[2]); pr[3] = fmaf(xj, wr.w, pr[3]);
        }
#pragma unroll
        for (int o = 16; o > 0; o >>= 1) {
#pragma unroll
            for (int q = 0; q < 4; q++) {
                pc[q] += __shfl_xor_sync(0xffffffffu, pc[q], o);
                pr[q] += __shfl_xor_sync(0xffffffffu, pr[q], o);
            }
        }
        if (tx == 0 && gn < NN) {
            *(float4*)(g_acol + gn * 4) = make_float4(pc[0], pc[1], pc[2], pc[3]);
            *(float4*)(g_arow + gn * 4) = make_float4(pr[0], pr[1], pr[2], pr[3]);
        }
    }
}

// ---------------------------------------------------------------------------
// CSR build: zero -> histogram -> exclusive scan -> scatter
// ---------------------------------------------------------------------------
__global__ void k_zero() {
    int i = blockIdx.x * blockDim.x + threadIdx.x;
    if (i < NN) g_cnt[i] = 0;
}

__global__ void k_hist(const int* __restrict__ erow) {
    int i = blockIdx.x * blockDim.x + threadIdx.x;
    if (i < NE) atomicAdd(&g_cnt[__ldg(erow + i)], 1);
}

// single block, 1024 threads: chunked serial + Hillis-Steele block scan
__global__ __launch_bounds__(1024) void k_scan() {
    __shared__ int ssum[1024];
    const int tid = threadIdx.x;
    const int CHUNK = (NN + 1023) / 1024;
    const int base = tid * CHUNK;

    int s = 0;
    for (int i = 0; i < CHUNK; i++) {
        int idx = base + i;
        if (idx < NN) s += g_cnt[idx];
    }
    ssum[tid] = s;
    __syncthreads();

    for (int off = 1; off < 1024; off <<= 1) {
        int add = (tid >= off) ? ssum[tid - off] : 0;
        __syncthreads();
        ssum[tid] += add;
        __syncthreads();
    }
    int run = ssum[tid] - s;   // exclusive prefix for this chunk

    for (int i = 0; i < CHUNK; i++) {
        int idx = base + i;
        if (idx < NN) {
            int c = g_cnt[idx];
            g_start[idx]  = run;
            g_cursor[idx] = run;
            run += c;
        }
    }
    if (tid == 1023) g_start[NN] = ssum[1023];
}

// ---------------------------------------------------------------------------
// Scatter: thread-per-edge (massive MLP). Computes the 4-channel softmax
// weight here and stores it with the source index into the CSR slot.
// ---------------------------------------------------------------------------
__global__ __launch_bounds__(256) void k_scatter(const int* __restrict__ erow,
                                                 const int* __restrict__ ecol,
                                                 const float* __restrict__ aW2,
                                                 const float* __restrict__ ab1,
                                                 const float* __restrict__ ab2) {
    int i = blockIdx.x * blockDim.x + threadIdx.x;
    if (i >= NE) return;

    int r  = __ldg(erow + i);
    int cc = __ldg(ecol + i);

    float4 ac = __ldg((const float4*)(g_acol + cc * 4));
    float4 ar = __ldg((const float4*)(g_arow + r * 4));
    float h0 = ac.x + ar.x + __ldg(ab1 + 0);
    float h1 = ac.y + ar.y + __ldg(ab1 + 1);
    float h2 = ac.z + ar.z + __ldg(ab1 + 2);
    float h3 = ac.w + ar.w + __ldg(ab1 + 3);

    float t0 = fmaf(h0, __ldg(aW2 + 0), fmaf(h1, __ldg(aW2 + 4), fmaf(h2, __ldg(aW2 + 8),  fmaf(h3, __ldg(aW2 + 12), __ldg(ab2 + 0)))));
    float t1 = fmaf(h0, __ldg(aW2 + 1), fmaf(h1, __ldg(aW2 + 5), fmaf(h2, __ldg(aW2 + 9),  fmaf(h3, __ldg(aW2 + 13), __ldg(ab2 + 1)))));
    float t2 = fmaf(h0, __ldg(aW2 + 2), fmaf(h1, __ldg(aW2 + 6), fmaf(h2, __ldg(aW2 + 10), fmaf(h3, __ldg(aW2 + 14), __ldg(ab2 + 2)))));
    float t3 = fmaf(h0, __ldg(aW2 + 3), fmaf(h1, __ldg(aW2 + 7), fmaf(h2, __ldg(aW2 + 11), fmaf(h3, __ldg(aW2 + 15), __ldg(ab2 + 3)))));

    float m = fmaxf(fmaxf(t0, t1), fmaxf(t2, t3));
    float e0 = __expf(t0 - m), e1 = __expf(t1 - m);
    float e2 = __expf(t2 - m), e3 = __expf(t3 - m);
    float inv = 1.f / (e0 + e1 + e2 + e3);

    int p = atomicAdd(&g_cursor[r], 1);
    g_ecc[p] = cc;
    *(float4*)(g_w + (size_t)p * 4) = make_float4(e0 * inv, e1 * inv, e2 * inv, e3 * inv);
}

// ---------------------------------------------------------------------------
// Kernel 2: warp-per-node PURE weighted gather-reduce, unrolled x8 with
// batched independent loads (MLP=8, single-hop L2 per edge). Fused with
// bias, per-channel L2 norm and classifier.
// ---------------------------------------------------------------------------
__global__ __launch_bounds__(256) void k_node(const float* __restrict__ bch,
                                              const float* __restrict__ Wcls,
                                              const float* __restrict__ bcls,
                                              float* __restrict__ out) {
    const int lane = threadIdx.x & 31;
    const int k = lane >> 3;                      // channel of this lane's float4
    const int n = (blockIdx.x * blockDim.x + threadIdx.x) >> 5;
    if (n >= NN) return;

    const int s_beg = __ldg(&g_start[n]);
    const int s_end = __ldg(&g_start[n + 1]);

    float a0 = 0.f, a1 = 0.f, a2 = 0.f, a3 = 0.f;

    int i = s_beg;
    for (; i + 7 < s_end; i += 8) {
        int   ci[8];
        float wk[8];
#pragma unroll
        for (int j = 0; j < 8; j++) ci[j] = __ldg(g_ecc + i + j);
#pragma unroll
        for (int j = 0; j < 8; j++) wk[j] = __ldg(g_w + (size_t)(i + j) * 4 + k);

        float4 v0 = __ldg((const float4*)(g_C + (size_t)ci[0] * HID + lane * 4));
        float4 v1 = __ldg((const float4*)(g_C + (size_t)ci[1] * HID + lane * 4));
        float4 v2 = __ldg((const float4*)(g_C + (size_t)ci[2] * HID + lane * 4));
        float4 v3 = __ldg((const float4*)(g_C + (size_t)ci[3] * HID + lane * 4));
        float4 v4 = __ldg((const float4*)(g_C + (size_t)ci[4] * HID + lane * 4));
        float4 v5 = __ldg((const float4*)(g_C + (size_t)ci[5] * HID + lane * 4));
        float4 v6 = __ldg((const float4*)(g_C + (size_t)ci[6] * HID + lane * 4));
        float4 v7 = __ldg((const float4*)(g_C + (size_t)ci[7] * HID + lane * 4));

        a0 = fmaf(wk[0], v0.x, a0); a1 = fmaf(wk[0], v0.y, a1);
        a2 = fmaf(wk[0], v0.z, a2); a3 = fmaf(wk[0], v0.w, a3);
        a0 = fmaf(wk[1], v1.x, a0); a1 = fmaf(wk[1], v1.y, a1);
        a2 = fmaf(wk[1], v1.z, a2); a3 = fmaf(wk[1], v1.w, a3);
        a0 = fmaf(wk[2], v2.x, a0); a1 = fmaf(wk[2], v2.y, a1);
        a2 = fmaf(wk[2], v2.z, a2); a3 = fmaf(wk[2], v2.w, a3);
        a0 = fmaf(wk[3], v3.x, a0); a1 = fmaf(wk[3], v3.y, a1);
        a2 = fmaf(wk[3], v3.z, a2); a3 = fmaf(wk[3], v3.w, a3);
        a0 = fmaf(wk[4], v4.x, a0); a1 = fmaf(wk[4], v4.y, a1);
        a2 = fmaf(wk[4], v4.z, a2); a3 = fmaf(wk[4], v4.w, a3);
        a0 = fmaf(wk[5], v5.x, a0); a1 = fmaf(wk[5], v5.y, a1);
        a2 = fmaf(wk[5], v5.z, a2); a3 = fmaf(wk[5], v5.w, a3);
        a0 = fmaf(wk[6], v6.x, a0); a1 = fmaf(wk[6], v6.y, a1);
        a2 = fmaf(wk[6], v6.z, a2); a3 = fmaf(wk[6], v6.w, a3);
        a0 = fmaf(wk[7], v7.x, a0); a1 = fmaf(wk[7], v7.y, a1);
        a2 = fmaf(wk[7], v7.z, a2); a3 = fmaf(wk[7], v7.w, a3);
    }
    for (; i < s_end; i++) {
        int cc = __ldg(g_ecc + i);
        float wk = __ldg(g_w + (size_t)i * 4 + k);
        float4 v = __ldg((const float4*)(g_C + (size_t)cc * HID + lane * 4));
        a0 = fmaf(wk, v.x, a0); a1 = fmaf(wk, v.y, a1);
        a2 = fmaf(wk, v.z, a2); a3 = fmaf(wk, v.w, a3);
    }

    // bias + per-channel L2 normalize
    float4 b = __ldg((const float4*)(bch + lane * 4));
    a0 += b.x; a1 += b.y; a2 += b.z; a3 += b.w;

    float ss = a0 * a0 + a1 * a1 + a2 * a2 + a3 * a3;
    ss += __shfl_xor_sync(0xffffffffu, ss, 1);
    ss += __shfl_xor_sync(0xffffffffu, ss, 2);
    ss += __shfl_xor_sync(0xffffffffu, ss, 4);   // 8-lane group = one channel
    float invn = 1.f / fmaxf(sqrtf(ss), 1e-12f);
    a0 *= invn; a1 *= invn; a2 *= invn; a3 *= invn;

    *(float4*)(out + (size_t)n * HID + lane * 4) = make_float4(a0, a1, a2, a3);

    // classifier
    float4 wc = __ldg((const float4*)(Wcls + lane * 4));
    float p = a0 * wc.x + a1 * wc.y + a2 * wc.z + a3 * wc.w;
#pragma unroll
    for (int o = 16; o > 0; o >>= 1) p += __shfl_xor_sync(0xffffffffu, p, o);
    if (lane == 0) out[(size_t)NN * HID + n] = p + __ldg(bcls);
}

// ---------------------------------------------------------------------------
extern "C" void kernel_launch(void* const* d_in, const int* in_sizes, int n_in,
                              void* d_out, int out_size) {
    const float* x     = (const float*)d_in[0];
    const int*   erow  = (const int*)  d_in[1];
    const int*   ecol  = (const int*)  d_in[2];
    const float* aW1   = (const float*)d_in[3];
    const float* ab1   = (const float*)d_in[4];
    const float* aW2   = (const float*)d_in[5];
    const float* ab2   = (const float*)d_in[6];
    const float* Wlin  = (const float*)d_in[7];
    const float* blin  = (const float*)d_in[8];
    const float* Wconv = (const float*)d_in[9];
    const float* bch   = (const float*)d_in[10];
    const float* Wcls  = (const float*)d_in[11];
    const float* bcls  = (const float*)d_in[12];
    float* out = (float*)d_out;

    k_combine<<<NF + 1, HID>>>(Wlin, blin, Wconv);
    k_zero<<<(NN + 255) / 256, 256>>>();
    k_gemm<<<(NN + TN - 1) / TN, 256>>>(x, aW1);
    k_hist<<<(NE + 255) / 256, 256>>>(erow);
    k_scan<<<1, 1024>>>();
    k_scatter<<<(NE + 255) / 256, 256>>>(erow, ecol, aW2, ab1, ab2);
    k_node<<<(NN * 32 + 255) / 256, 256>>>(bch, Wcls, bcls, out);
}